// round 5
// baseline (speedup 1.0000x reference)
#include <cuda_runtime.h>

// x: [B=16, T=4096, D=1024] f32, out: [B, D] = sum over T.
// Grid = 444 = 3 * 148 SMs: every SM gets exactly 3 resident CTAs and
// per-SM bytes are balanced to +-1 row (vs 4-vs-3 CTA imbalance at grid=512).
// Each block owns rows [i*R/G, (i+1)*R/G) of the flattened [B*T] row space
// (147 or 148 rows); a range straddles at most one batch boundary -> <=2
// segments, each written to a static partial slot (2i+seg). Last ticket per
// batch reduces that batch's slots in fixed ascending order (deterministic)
// and resets the ticket (graph-replay safe).

#define B_DIM 16
#define T_DIM 4096
#define D_DIM 1024
#define D4 (D_DIM / 4)            // 256 float4 per row
#define TOTAL_ROWS (B_DIM * T_DIM)  // 65536
#define GRID 444

// Partial slots: [2*GRID][D] f32 = 3.55 MiB.
__device__ float g_partial[2 * GRID * D_DIM];
// Per-batch arrival tickets (zero-init; reset by reducer each run).
__device__ int g_count[B_DIM];

// Block index whose range contains flat row r.
__device__ __forceinline__ int block_of_row(int r) {
    return (int)(((long long)(r + 1) * GRID - 1) / TOTAL_ROWS);
}

__global__ __launch_bounds__(256, 8)
void sum_balanced(const float* __restrict__ x, float* __restrict__ out) {
    const int i   = blockIdx.x;       // 0..443
    const int tid = threadIdx.x;      // 0..255 -> one float4 column

    const int r0 = (int)((long long)i       * TOTAL_ROWS / GRID);
    const int r1 = (int)((long long)(i + 1) * TOTAL_ROWS / GRID);
    const int b0 = r0 / T_DIM;        // batch the block starts in
    const int bsplit = (b0 + 1) * T_DIM;  // first row of next batch

    const float4* __restrict__ x4 = reinterpret_cast<const float4*>(x);
    float4* __restrict__ p4 = reinterpret_cast<float4*>(g_partial);
    __shared__ int s_ticket;

    // Up to two segments: [r0, min(r1,bsplit)) in batch b0 (slot 2i),
    //                     [bsplit, r1) in batch b0+1 (slot 2i+1).
    #pragma unroll
    for (int seg = 0; seg < 2; ++seg) {
        const int rs = seg ? bsplit : r0;
        const int re = seg ? r1 : (r1 < bsplit ? r1 : bsplit);
        if (rs >= re) continue;
        const int b = b0 + seg;

        float4 acc = make_float4(0.f, 0.f, 0.f, 0.f);
        #pragma unroll 4
        for (int r = rs; r < re; ++r) {
            float4 v = __ldg(x4 + (size_t)r * D4 + tid);
            acc.x += v.x; acc.y += v.y; acc.z += v.z; acc.w += v.w;
        }
        p4[(size_t)(2 * i + seg) * D4 + tid] = acc;

        __threadfence();
        if (tid == 0) s_ticket = atomicAdd(&g_count[b], 1);
        __syncthreads();
        const int my_ticket = s_ticket;
        __syncthreads();   // s_ticket reused next seg

        // Number of blocks contributing a segment to batch b.
        const int iF = block_of_row(b * T_DIM);
        const int iL = block_of_row(b * T_DIM + T_DIM - 1);
        const int nseg = iL - iF + 1;

        if (my_ticket == nseg - 1) {
            // Last finisher for batch b: sum its slots in fixed order.
            float4 rsum = make_float4(0.f, 0.f, 0.f, 0.f);
            for (int j = iF; j <= iL; ++j) {
                // Block j's segment for b: slot 2j if j starts in b, else 2j+1
                // (only possible for j == iF, which may start in batch b-1).
                const int jr0 = (int)((long long)j * TOTAL_ROWS / GRID);
                const int slot = 2 * j + ((jr0 / T_DIM) == b ? 0 : 1);
                float4 v = p4[(size_t)slot * D4 + tid];
                rsum.x += v.x; rsum.y += v.y; rsum.z += v.z; rsum.w += v.w;
            }
            reinterpret_cast<float4*>(out + (size_t)b * D_DIM)[tid] = rsum;
            if (tid == 0) g_count[b] = 0;   // graph-replay safe
        }
    }
}

extern "C" void kernel_launch(void* const* d_in, const int* in_sizes, int n_in,
                              void* d_out, int out_size) {
    const float* x = (const float*)d_in[0];
    float* out = (float*)d_out;
    sum_balanced<<<GRID, 256>>>(x, out);
}

// round 6
// speedup vs baseline: 1.1372x; 1.1372x over previous
#include <cuda_runtime.h>

// x: [B=16, T=4096, D=1024] f32, out: [B, D] = sum over T.
// Phase1: proven best config (512 blocks x 256 thr, unroll 8, __ldg),
//         each block sums 128 rows -> partial [b][s][D].
// Phase2: one WARP per output float4 (4096 warps): lane l loads partial
//         slot l, 5-step shfl butterfly (fixed tree -> deterministic).
//         Input is L2-dirty-resident (4 MiB just written) -> latency-bound,
//         ~1.5-2us instead of the 5.25us serial version.

#define B_DIM 16
#define T_DIM 4096
#define D_DIM 1024
#define D4 (D_DIM / 4)              // 256 float4 per row
#define SPLITS 32
#define ROWS_PER_BLK (T_DIM / SPLITS)   // 128

// Scratch partials: [B, SPLITS, D] f32 = 2 MiB.
__device__ float g_partial[B_DIM * SPLITS * D_DIM];

__global__ __launch_bounds__(256, 8)
void sum_phase1(const float* __restrict__ x) {
    const int b = blockIdx.x;          // 0..15
    const int s = blockIdx.y;          // 0..31
    const int tid = threadIdx.x;       // 0..255 -> one float4 column

    const float4* __restrict__ xp = reinterpret_cast<const float4*>(
        x + (size_t)b * T_DIM * D_DIM + (size_t)s * ROWS_PER_BLK * D_DIM);

    float4 acc = make_float4(0.f, 0.f, 0.f, 0.f);

    #pragma unroll 8
    for (int r = 0; r < ROWS_PER_BLK; ++r) {
        float4 v = __ldg(xp + (size_t)r * D4 + tid);
        acc.x += v.x; acc.y += v.y; acc.z += v.z; acc.w += v.w;
    }

    reinterpret_cast<float4*>(
        g_partial + (size_t)(b * SPLITS + s) * D_DIM)[tid] = acc;
}

__global__ __launch_bounds__(256)
void sum_phase2(float* __restrict__ out) {
    // 4096 warps total; warp w owns output float4 index w.
    const int gtid = blockIdx.x * blockDim.x + threadIdx.x;
    const int w = gtid >> 5;           // 0..4095
    const int l = gtid & 31;           // lane = partial slot s
    const int b = w >> 8;              // w / 256
    const int q = w & 255;             // float4 column within D

    const float4* __restrict__ p4 = reinterpret_cast<const float4*>(g_partial);
    float4 v = p4[(size_t)(b * SPLITS + l) * D4 + q];

    // Butterfly reduction over the 32 lanes (fixed tree -> deterministic).
    #pragma unroll
    for (int off = 16; off > 0; off >>= 1) {
        v.x += __shfl_down_sync(0xffffffffu, v.x, off);
        v.y += __shfl_down_sync(0xffffffffu, v.y, off);
        v.z += __shfl_down_sync(0xffffffffu, v.z, off);
        v.w += __shfl_down_sync(0xffffffffu, v.w, off);
    }

    if (l == 0)
        reinterpret_cast<float4*>(out)[(size_t)b * D4 + q] = v;
}

extern "C" void kernel_launch(void* const* d_in, const int* in_sizes, int n_in,
                              void* d_out, int out_size) {
    const float* x = (const float*)d_in[0];
    float* out = (float*)d_out;

    dim3 g1(B_DIM, SPLITS);
    sum_phase1<<<g1, 256>>>(x);

    // 4096 warps = 131072 threads = 512 blocks x 256.
    sum_phase2<<<512, 256>>>(out);
}

// round 7
// speedup vs baseline: 1.1457x; 1.0075x over previous
#include <cuda_runtime.h>

// x: [B=16, T=4096, D=1024] f32, out: [B, D] = sum over T.
// Single kernel, zero cross-block communication: split D (not T).
// Grid = (16 batches, 32 column-chunks) = 512 blocks (proven BW-optimal
// shape). Each block owns an 8-float4 (128B) column strip and walks all
// 4096 rows: thread = (rowgroup rg=tid>>3 in 0..31, col c=tid&7), 128
// iterations. Warp load = 4 rows x 128B = 4 full lines, perfectly
// coalesced; column strips partition each row -> no duplicate traffic.
// Epilogue: 5-step smem tree over the 32 rowgroups (fixed order ->
// deterministic), 8 threads write float4s directly to out. No scratch,
// no atomics, no second kernel, no 5us reduction-stage barrier.

#define B_DIM 16
#define T_DIM 4096
#define D_DIM 1024
#define D4 (D_DIM / 4)          // 256 float4 per row
#define CHUNKS 32               // column chunks per batch
#define C4 (D4 / CHUNKS)        // 8 float4 per chunk
#define RG 32                   // rowgroups (rows in flight per iteration)
#define ITERS (T_DIM / RG)      // 128

__global__ __launch_bounds__(256, 8)
void sum_colsplit(const float* __restrict__ x, float* __restrict__ out) {
    const int b     = blockIdx.x;       // 0..15
    const int chunk = blockIdx.y;       // 0..31
    const int tid   = threadIdx.x;      // 0..255
    const int c  = tid & (C4 - 1);      // 0..7  : float4 column within chunk
    const int rg = tid >> 3;            // 0..31 : rowgroup

    // Base: batch b, row rg, column chunk*C4 + c (in float4 units).
    const float4* __restrict__ xp = reinterpret_cast<const float4*>(x)
        + (size_t)b * T_DIM * D4 + (size_t)rg * D4 + (size_t)chunk * C4 + c;

    float4 acc = make_float4(0.f, 0.f, 0.f, 0.f);

    #pragma unroll 8
    for (int it = 0; it < ITERS; ++it) {
        float4 v = __ldg(xp + (size_t)it * RG * D4);
        acc.x += v.x; acc.y += v.y; acc.z += v.z; acc.w += v.w;
    }

    // Reduce the 32 rowgroups per column via smem tree (fixed order).
    __shared__ float4 s_acc[256];
    s_acc[rg * C4 + c] = acc;
    __syncthreads();

    #pragma unroll
    for (int off = RG / 2; off > 0; off >>= 1) {
        if (rg < off) {
            float4 a = s_acc[rg * C4 + c];
            float4 v = s_acc[(rg + off) * C4 + c];
            a.x += v.x; a.y += v.y; a.z += v.z; a.w += v.w;
            s_acc[rg * C4 + c] = a;
        }
        __syncthreads();
    }

    if (rg == 0) {
        reinterpret_cast<float4*>(out)[(size_t)b * D4 + chunk * C4 + c] =
            s_acc[c];
    }
}

extern "C" void kernel_launch(void* const* d_in, const int* in_sizes, int n_in,
                              void* d_out, int out_size) {
    const float* x = (const float*)d_in[0];
    float* out = (float*)d_out;

    dim3 grid(B_DIM, CHUNKS);
    sum_colsplit<<<grid, 256>>>(x, out);
}